// round 1
// baseline (speedup 1.0000x reference)
#include <cuda_runtime.h>
#include <cuda_bf16.h>
#include <math.h>

// Problem constants
#define BATCH   4
#define SEQLEN  2048
#define DMODEL  512
#define DSTATE  64
#define MTOT    (BATCH * SEQLEN)   // 8192

// Intermediate buffers (no cudaMalloc allowed)
__device__ float g_u[BATCH * DMODEL * SEQLEN];   // [b][d][l]  16 MB
__device__ float g_y[MTOT * DMODEL];             // [b*l][d]   16 MB

// ---------------------------------------------------------------------------
// Tiled SGEMM:  out[m,n] = sum_k A[m,k] * W[n,k] + bias[n]
// MODE 0: out -> C param (normal [M,N] layout)
// MODE 1: A from param, out -> g_u transposed to [b][n][l]
// M=8192, N=512, K=512 hardcoded.
// ---------------------------------------------------------------------------
#define BM 64
#define BN 64
#define BK 16

template <int MODE>
__global__ __launch_bounds__(256) void gemm_nt(const float* __restrict__ Ain,
                                               const float* __restrict__ W,
                                               const float* __restrict__ bias,
                                               float* __restrict__ Cout)
{
    __shared__ float As[BK][BM];
    __shared__ float Bs[BK][BN];
    __shared__ float Tr[(MODE == 1) ? BM : 1][(MODE == 1) ? (BN + 1) : 1];

    const int tid = threadIdx.x;
    const int tx  = tid & 15;        // n group
    const int ty  = tid >> 4;        // m group
    const int n0  = blockIdx.x * BN;
    const int m0  = blockIdx.y * BM;

    const float* A = (MODE == 0) ? g_y : Ain;

    // load indices: each thread loads one float4 from A and one from W
    const int lrow = tid >> 2;       // 0..63
    const int lcol = (tid & 3) * 4;  // 0,4,8,12

    float acc[4][4];
#pragma unroll
    for (int i = 0; i < 4; i++)
#pragma unroll
        for (int j = 0; j < 4; j++) acc[i][j] = 0.0f;

    for (int kt = 0; kt < 512; kt += BK) {
        float4 av = *(const float4*)(A + (size_t)(m0 + lrow) * 512 + kt + lcol);
        float4 wv = *(const float4*)(W + (size_t)(n0 + lrow) * 512 + kt + lcol);
        As[lcol + 0][lrow] = av.x;
        As[lcol + 1][lrow] = av.y;
        As[lcol + 2][lrow] = av.z;
        As[lcol + 3][lrow] = av.w;
        Bs[lcol + 0][lrow] = wv.x;
        Bs[lcol + 1][lrow] = wv.y;
        Bs[lcol + 2][lrow] = wv.z;
        Bs[lcol + 3][lrow] = wv.w;
        __syncthreads();

#pragma unroll
        for (int kk = 0; kk < BK; kk++) {
            float4 a = *(const float4*)(&As[kk][ty * 4]);
            float4 b = *(const float4*)(&Bs[kk][tx * 4]);
            acc[0][0] = fmaf(a.x, b.x, acc[0][0]);
            acc[0][1] = fmaf(a.x, b.y, acc[0][1]);
            acc[0][2] = fmaf(a.x, b.z, acc[0][2]);
            acc[0][3] = fmaf(a.x, b.w, acc[0][3]);
            acc[1][0] = fmaf(a.y, b.x, acc[1][0]);
            acc[1][1] = fmaf(a.y, b.y, acc[1][1]);
            acc[1][2] = fmaf(a.y, b.z, acc[1][2]);
            acc[1][3] = fmaf(a.y, b.w, acc[1][3]);
            acc[2][0] = fmaf(a.z, b.x, acc[2][0]);
            acc[2][1] = fmaf(a.z, b.y, acc[2][1]);
            acc[2][2] = fmaf(a.z, b.z, acc[2][2]);
            acc[2][3] = fmaf(a.z, b.w, acc[2][3]);
            acc[3][0] = fmaf(a.w, b.x, acc[3][0]);
            acc[3][1] = fmaf(a.w, b.y, acc[3][1]);
            acc[3][2] = fmaf(a.w, b.z, acc[3][2]);
            acc[3][3] = fmaf(a.w, b.w, acc[3][3]);
        }
        __syncthreads();
    }

    float4 bv = *(const float4*)(bias + n0 + tx * 4);

    if (MODE == 0) {
#pragma unroll
        for (int i = 0; i < 4; i++) {
            float4 v;
            v.x = acc[i][0] + bv.x;
            v.y = acc[i][1] + bv.y;
            v.z = acc[i][2] + bv.z;
            v.w = acc[i][3] + bv.w;
            *(float4*)(Cout + (size_t)(m0 + ty * 4 + i) * 512 + n0 + tx * 4) = v;
        }
    } else {
        // stage through shared, write transposed to g_u[b][n][l]
#pragma unroll
        for (int i = 0; i < 4; i++) {
            Tr[ty * 4 + i][tx * 4 + 0] = acc[i][0] + bv.x;
            Tr[ty * 4 + i][tx * 4 + 1] = acc[i][1] + bv.y;
            Tr[ty * 4 + i][tx * 4 + 2] = acc[i][2] + bv.z;
            Tr[ty * 4 + i][tx * 4 + 3] = acc[i][3] + bv.w;
        }
        __syncthreads();
        const int b  = m0 >> 11;          // m0 / 2048
        const int l0 = m0 & 2047;
#pragma unroll
        for (int idx = tid; idx < BM * BN; idx += 256) {
            int dp = idx >> 6;   // 0..63  (n within tile)
            int lp = idx & 63;   // 0..63  (l within tile), consecutive -> coalesced
            g_u[((size_t)(b * DMODEL + n0 + dp) << 11) + l0 + lp] = Tr[lp][dp];
        }
    }
}

// ---------------------------------------------------------------------------
// SSM recurrence scan. One warp per (b,d) sequence; 2 states per lane.
// z_n(t) = r_n * z_n(t-1) + u(t);  y(t) = sum_n coef_n z_n(t) + D_d u(t)
// ---------------------------------------------------------------------------
__global__ __launch_bounds__(256) void s4_scan(const float* __restrict__ A_log,
                                               const float* __restrict__ Bp,
                                               const float* __restrict__ Cp,
                                               const float* __restrict__ Dp,
                                               const float* __restrict__ dt)
{
    const int warp = (blockIdx.x * blockDim.x + threadIdx.x) >> 5;
    const int lane = threadIdx.x & 31;
    const int d = warp & (DMODEL - 1);
    const int b = warp >> 9;

    const float dtd = dt[d];
    const int i0 = d * DSTATE + lane;
    const int i1 = i0 + 32;

    const float a0 = -expf(A_log[i0]);
    const float a1 = -expf(A_log[i1]);
    const float r0 = expf(a0 * dtd);
    const float r1 = expf(a1 * dtd);
    const float c0 = Cp[i0] * Bp[i0] * dtd;
    const float c1 = Cp[i1] * Bp[i1] * dtd;
    const float Dd = Dp[d];

    const float* ub = g_u + ((size_t)(b * DMODEL + d) << 11);
    float* yb = g_y + (size_t)(b << 11) * DMODEL + d;

    float z0 = 0.0f, z1 = 0.0f;

    for (int t0 = 0; t0 < SEQLEN; t0 += 32) {
        float uv = ub[t0 + lane];
#pragma unroll
        for (int i = 0; i < 32; i++) {
            float uu = __shfl_sync(0xffffffffu, uv, i);
            z0 = fmaf(r0, z0, uu);
            z1 = fmaf(r1, z1, uu);
            float p = fmaf(c0, z0, c1 * z1);
            p += __shfl_xor_sync(0xffffffffu, p, 16);
            p += __shfl_xor_sync(0xffffffffu, p, 8);
            p += __shfl_xor_sync(0xffffffffu, p, 4);
            p += __shfl_xor_sync(0xffffffffu, p, 2);
            p += __shfl_xor_sync(0xffffffffu, p, 1);
            if (lane == 0) yb[(size_t)(t0 + i) * DMODEL] = fmaf(Dd, uu, p);
        }
    }
}

// ---------------------------------------------------------------------------
extern "C" void kernel_launch(void* const* d_in, const int* in_sizes, int n_in,
                              void* d_out, int out_size)
{
    const float* x     = (const float*)d_in[0];
    const float* W_in  = (const float*)d_in[1];
    const float* b_in  = (const float*)d_in[2];
    const float* A_log = (const float*)d_in[3];
    const float* B     = (const float*)d_in[4];
    const float* C     = (const float*)d_in[5];
    const float* D     = (const float*)d_in[6];
    const float* dt    = (const float*)d_in[7];
    const float* W_out = (const float*)d_in[8];
    const float* b_out = (const float*)d_in[9];
    float* out = (float*)d_out;

    dim3 ggrid(DMODEL / BN, MTOT / BM);   // (8, 128)

    // 1) in_proj, output transposed to g_u[b][d][l]
    gemm_nt<1><<<ggrid, 256>>>(x, W_in, b_in, nullptr);

    // 2) SSM recurrence: g_u -> g_y ([b*l][d])
    s4_scan<<<(BATCH * DMODEL) / 8, 256>>>(A_log, B, C, D, dt);

    // 3) out_proj: g_y -> out
    gemm_nt<0><<<ggrid, 256>>>(nullptr, W_out, b_out, out);
}

// round 2
// speedup vs baseline: 1.5986x; 1.5986x over previous
#include <cuda_runtime.h>
#include <cuda_bf16.h>
#include <math.h>

// Problem constants
#define BATCH   4
#define SEQLEN  2048
#define DMODEL  512
#define DSTATE  64
#define MTOT    (BATCH * SEQLEN)   // 8192

// Intermediate buffers (no cudaMalloc allowed)
__device__ float g_u[BATCH * DMODEL * SEQLEN];   // [b][d][l]  16 MB
__device__ float g_y[BATCH * DMODEL * SEQLEN];   // [b][d][l]  16 MB (K-major for GEMM2)

// ---------------------------------------------------------------------------
// Tiled SGEMM 128x128x8, 8x8 microtile, double-buffered shared memory.
//   out[m,n] = sum_k A[m,k] * W[n,k] + bias[n]
// MODE 1: A = x row-major [m][k]; epilogue writes TRANSPOSED to g_u[b][d][l].
// MODE 2: A = g_y K-major [k][m] (i.e. [b*512+d][l]); epilogue row-major out.
// M=8192, N=512, K=512.
// ---------------------------------------------------------------------------
#define BM 128
#define BN 128
#define KD 8

template <int MODE>
__global__ __launch_bounds__(256) void gemm_nt(const float* __restrict__ Ain,
                                               const float* __restrict__ W,
                                               const float* __restrict__ bias,
                                               float* __restrict__ Cout)
{
    __shared__ float As[2][KD][BM + 4];
    __shared__ float Bs[2][KD][BN + 4];

    const int tid = threadIdx.x;
    const int tx  = tid & 15;
    const int ty  = tid >> 4;
    const int n0  = blockIdx.x * BN;
    const int m0  = blockIdx.y * BM;

    const float* A = (MODE == 2) ? g_y : Ain;

    // W load mapping (row-major [n][k], transposed into Bs via scalar stores)
    const int wrow = tid >> 1;           // 0..127
    const int wk   = (tid & 1) * 4;      // 0 or 4
    // MODE 2 A load mapping (K-major, direct float4 store)
    const int akr  = tid >> 5;           // 0..7
    const int amc  = (tid & 31) * 4;     // 0..124
    const int bb   = m0 >> 11;           // batch of this m-tile
    const int l0   = m0 & 2047;

    float acc[8][8];
#pragma unroll
    for (int i = 0; i < 8; i++)
#pragma unroll
        for (int j = 0; j < 8; j++) acc[i][j] = 0.0f;

    // prologue loads (kt = 0)
    float4 pA, pW;
    if (MODE == 1) pA = *(const float4*)(A + (size_t)(m0 + wrow) * 512 + wk);
    else           pA = *(const float4*)(A + ((size_t)(bb * 512 + akr) << 11) + l0 + amc);
    pW = *(const float4*)(W + (size_t)(n0 + wrow) * 512 + wk);

#pragma unroll 1
    for (int kt = 0; kt < 512; kt += KD) {
        const int buf = (kt >> 3) & 1;
        // store current tile to smem
        if (MODE == 1) {
            As[buf][wk + 0][wrow] = pA.x;
            As[buf][wk + 1][wrow] = pA.y;
            As[buf][wk + 2][wrow] = pA.z;
            As[buf][wk + 3][wrow] = pA.w;
        } else {
            *(float4*)&As[buf][akr][amc] = pA;
        }
        Bs[buf][wk + 0][wrow] = pW.x;
        Bs[buf][wk + 1][wrow] = pW.y;
        Bs[buf][wk + 2][wrow] = pW.z;
        Bs[buf][wk + 3][wrow] = pW.w;
        __syncthreads();

        // prefetch next tile into registers
        const int ktn = kt + KD;
        if (ktn < 512) {
            if (MODE == 1) pA = *(const float4*)(A + (size_t)(m0 + wrow) * 512 + ktn + wk);
            else           pA = *(const float4*)(A + ((size_t)(bb * 512 + ktn + akr) << 11) + l0 + amc);
            pW = *(const float4*)(W + (size_t)(n0 + wrow) * 512 + ktn + wk);
        }

        // compute on buf
#pragma unroll
        for (int kk = 0; kk < KD; kk++) {
            float4 a0 = *(const float4*)&As[buf][kk][ty * 4];
            float4 a1 = *(const float4*)&As[buf][kk][64 + ty * 4];
            float4 b0 = *(const float4*)&Bs[buf][kk][tx * 4];
            float4 b1 = *(const float4*)&Bs[buf][kk][64 + tx * 4];
            float av[8] = {a0.x, a0.y, a0.z, a0.w, a1.x, a1.y, a1.z, a1.w};
            float bv[8] = {b0.x, b0.y, b0.z, b0.w, b1.x, b1.y, b1.z, b1.w};
#pragma unroll
            for (int i = 0; i < 8; i++)
#pragma unroll
                for (int j = 0; j < 8; j++)
                    acc[i][j] = fmaf(av[i], bv[j], acc[i][j]);
        }
        __syncthreads();
    }

    if (MODE == 2) {
        float4 bv0 = *(const float4*)(bias + n0 + tx * 4);
        float4 bv1 = *(const float4*)(bias + n0 + 64 + tx * 4);
#pragma unroll
        for (int i = 0; i < 8; i++) {
            const int row = m0 + ((i < 4) ? (ty * 4 + i) : (64 + ty * 4 + i - 4));
            float4 v0, v1;
            v0.x = acc[i][0] + bv0.x; v0.y = acc[i][1] + bv0.y;
            v0.z = acc[i][2] + bv0.z; v0.w = acc[i][3] + bv0.w;
            v1.x = acc[i][4] + bv1.x; v1.y = acc[i][5] + bv1.y;
            v1.z = acc[i][6] + bv1.z; v1.w = acc[i][7] + bv1.w;
            *(float4*)(Cout + (size_t)row * 512 + n0 + tx * 4) = v0;
            *(float4*)(Cout + (size_t)row * 512 + n0 + 64 + tx * 4) = v1;
        }
    } else {
        // write transposed: g_u[b][col][l], 32B-contiguous chunks per row per warp
#pragma unroll
        for (int j = 0; j < 8; j++) {
            const int col = n0 + ((j < 4) ? (tx * 4 + j) : (64 + tx * 4 + j - 4));
            const float bj = __ldg(bias + col);
            float4 v0, v1;
            v0.x = acc[0][j] + bj; v0.y = acc[1][j] + bj;
            v0.z = acc[2][j] + bj; v0.w = acc[3][j] + bj;
            v1.x = acc[4][j] + bj; v1.y = acc[5][j] + bj;
            v1.z = acc[6][j] + bj; v1.w = acc[7][j] + bj;
            float* base = g_u + ((size_t)(bb * 512 + col) << 11) + l0;
            *(float4*)(base + ty * 4) = v0;
            *(float4*)(base + 64 + ty * 4) = v1;
        }
    }
}

// ---------------------------------------------------------------------------
// SSM recurrence scan. One warp per (b,d); 2 states/lane.
// Per 32-step chunk: per-lane partial accumulation + one tree reduction.
// Writes y in K-major [b][d][l] (coalesced), consumed directly by GEMM2.
// ---------------------------------------------------------------------------
__global__ __launch_bounds__(256) void s4_scan(const float* __restrict__ A_log,
                                               const float* __restrict__ Bp,
                                               const float* __restrict__ Cp,
                                               const float* __restrict__ Dp,
                                               const float* __restrict__ dt)
{
    const int warp = (blockIdx.x * blockDim.x + threadIdx.x) >> 5;
    const int lane = threadIdx.x & 31;
    const int d = warp & (DMODEL - 1);
    const int b = warp >> 9;

    const float dtd = dt[d];
    const int i0 = d * DSTATE + lane;
    const int i1 = i0 + 32;

    const float r0 = expf(-expf(A_log[i0]) * dtd);
    const float r1 = expf(-expf(A_log[i1]) * dtd);
    const float c0 = Cp[i0] * Bp[i0] * dtd;
    const float c1 = Cp[i1] * Bp[i1] * dtd;
    const float Dd = Dp[d];

    const float* ub = g_u + ((size_t)(b * DMODEL + d) << 11);
    float*       yb = g_y + ((size_t)(b * DMODEL + d) << 11);

    float z0 = 0.0f, z1 = 0.0f;

    for (int t0 = 0; t0 < SEQLEN; t0 += 32) {
        const float uv = ub[t0 + lane];
        float p[32];
#pragma unroll
        for (int i = 0; i < 32; i++) {
            const float uu = __shfl_sync(0xffffffffu, uv, i);
            z0 = fmaf(r0, z0, uu);
            z1 = fmaf(r1, z1, uu);
            p[i] = fmaf(c0, z0, c1 * z1);
        }
        // tree-reduce 32 register vectors across 32 lanes:
        // after all stages, lane j holds sum over lanes of p[j].
        const bool h16 = (lane & 16);
        float s16[16];
#pragma unroll
        for (int k = 0; k < 16; k++) {
            const float keep = h16 ? p[k + 16] : p[k];
            const float send = h16 ? p[k] : p[k + 16];
            s16[k] = keep + __shfl_xor_sync(0xffffffffu, send, 16);
        }
        const bool h8 = (lane & 8);
        float s8[8];
#pragma unroll
        for (int k = 0; k < 8; k++) {
            const float keep = h8 ? s16[k + 8] : s16[k];
            const float send = h8 ? s16[k] : s16[k + 8];
            s8[k] = keep + __shfl_xor_sync(0xffffffffu, send, 8);
        }
        const bool h4 = (lane & 4);
        float s4[4];
#pragma unroll
        for (int k = 0; k < 4; k++) {
            const float keep = h4 ? s8[k + 4] : s8[k];
            const float send = h4 ? s8[k] : s8[k + 4];
            s4[k] = keep + __shfl_xor_sync(0xffffffffu, send, 4);
        }
        const bool h2 = (lane & 2);
        float s2[2];
#pragma unroll
        for (int k = 0; k < 2; k++) {
            const float keep = h2 ? s4[k + 2] : s4[k];
            const float send = h2 ? s4[k] : s4[k + 2];
            s2[k] = keep + __shfl_xor_sync(0xffffffffu, send, 2);
        }
        const bool h1 = (lane & 1);
        const float keep = h1 ? s2[1] : s2[0];
        const float send = h1 ? s2[0] : s2[1];
        const float tot = keep + __shfl_xor_sync(0xffffffffu, send, 1);

        yb[t0 + lane] = fmaf(Dd, uv, tot);   // coalesced 128B store
    }
}

// ---------------------------------------------------------------------------
extern "C" void kernel_launch(void* const* d_in, const int* in_sizes, int n_in,
                              void* d_out, int out_size)
{
    const float* x     = (const float*)d_in[0];
    const float* W_in  = (const float*)d_in[1];
    const float* b_in  = (const float*)d_in[2];
    const float* A_log = (const float*)d_in[3];
    const float* B     = (const float*)d_in[4];
    const float* C     = (const float*)d_in[5];
    const float* D     = (const float*)d_in[6];
    const float* dt    = (const float*)d_in[7];
    const float* W_out = (const float*)d_in[8];
    const float* b_out = (const float*)d_in[9];
    float* out = (float*)d_out;

    dim3 ggrid(DMODEL / BN, MTOT / BM);   // (4, 64) = 256 blocks

    // 1) in_proj, output transposed to g_u[b][d][l]
    gemm_nt<1><<<ggrid, 256>>>(x, W_in, b_in, nullptr);

    // 2) SSM recurrence: g_u -> g_y ([b][d][l], K-major)
    s4_scan<<<(BATCH * DMODEL) / 8, 256>>>(A_log, B, C, D, dt);

    // 3) out_proj: g_y (K-major) -> out
    gemm_nt<2><<<ggrid, 256>>>(nullptr, W_out, b_out, out);
}

// round 4
// speedup vs baseline: 2.7420x; 1.7153x over previous
#include <cuda_runtime.h>
#include <cuda_fp16.h>
#include <math.h>
#include <stdint.h>

// Problem constants
#define BATCH   4
#define SEQLEN  2048
#define DMODEL  512
#define DSTATE  64
#define MTOT    (BATCH * SEQLEN)   // 8192

// ---------------------------------------------------------------------------
// Device scratch (no cudaMalloc allowed)
// ---------------------------------------------------------------------------
__device__ float g_u[BATCH * DMODEL * SEQLEN];    // [b][d][l] fp32
__device__ float g_y[BATCH * DMODEL * SEQLEN];    // [b][d][l] fp32
__device__ __half g_ah[MTOT * DMODEL];            // activations hi [m][k]
__device__ __half g_al[MTOT * DMODEL];            // activations lo [m][k]
__device__ __half g_wh[2 * DMODEL * DMODEL];      // W_in | W_out hi
__device__ __half g_wl[2 * DMODEL * DMODEL];      // W_in | W_out lo

// ---------------------------------------------------------------------------
// PTX helpers (sm_80-era: cp.async + ldmatrix + mma.sync — legal on sm_100)
// ---------------------------------------------------------------------------
__device__ __forceinline__ uint32_t smem_u32(const void* p) {
    uint32_t a;
    asm("{ .reg .u64 t; cvta.to.shared.u64 t, %1; cvt.u32.u64 %0, t; }" : "=r"(a) : "l"(p));
    return a;
}
__device__ __forceinline__ void cpasync16(uint32_t s, const void* g) {
    asm volatile("cp.async.cg.shared.global [%0], [%1], 16;" :: "r"(s), "l"(g));
}
__device__ __forceinline__ void cp_commit() {
    asm volatile("cp.async.commit_group;" ::: "memory");
}
__device__ __forceinline__ void ldsm4(uint32_t a, uint32_t* r) {
    asm volatile("ldmatrix.sync.aligned.m8n8.x4.shared.b16 {%0,%1,%2,%3}, [%4];"
                 : "=r"(r[0]), "=r"(r[1]), "=r"(r[2]), "=r"(r[3]) : "r"(a));
}
__device__ __forceinline__ void mma16816(float* c, const uint32_t* a, const uint32_t* b) {
    asm volatile(
        "mma.sync.aligned.m16n8k16.row.col.f32.f16.f16.f32 "
        "{%0,%1,%2,%3}, {%4,%5,%6,%7}, {%8,%9}, {%0,%1,%2,%3};"
        : "+f"(c[0]), "+f"(c[1]), "+f"(c[2]), "+f"(c[3])
        : "r"(a[0]), "r"(a[1]), "r"(a[2]), "r"(a[3]), "r"(b[0]), "r"(b[1]));
}

// ---------------------------------------------------------------------------
// Split-precision conversion:  v -> (fp16 hi, fp16 lo)
// ---------------------------------------------------------------------------
__global__ __launch_bounds__(256) void convert_split(const float* __restrict__ in,
                                                     __half* __restrict__ hi,
                                                     __half* __restrict__ lo,
                                                     int n4)
{
    int i = blockIdx.x * 256 + threadIdx.x;
    if (i >= n4) return;
    float4 v = ((const float4*)in)[i];
    __half h0 = __float2half_rn(v.x);
    __half h1 = __float2half_rn(v.y);
    __half h2 = __float2half_rn(v.z);
    __half h3 = __float2half_rn(v.w);
    __half l0 = __float2half_rn(v.x - __half2float(h0));
    __half l1 = __float2half_rn(v.y - __half2float(h1));
    __half l2 = __float2half_rn(v.z - __half2float(h2));
    __half l3 = __float2half_rn(v.w - __half2float(h3));
    uint2 ph, pl;
    ph.x = (uint32_t)__half_as_ushort(h0) | ((uint32_t)__half_as_ushort(h1) << 16);
    ph.y = (uint32_t)__half_as_ushort(h2) | ((uint32_t)__half_as_ushort(h3) << 16);
    pl.x = (uint32_t)__half_as_ushort(l0) | ((uint32_t)__half_as_ushort(l1) << 16);
    pl.y = (uint32_t)__half_as_ushort(l2) | ((uint32_t)__half_as_ushort(l3) << 16);
    ((uint2*)hi)[i] = ph;
    ((uint2*)lo)[i] = pl;
}

// ---------------------------------------------------------------------------
// Transpose + split-convert: g_y [b][d][l] fp32 -> g_ah/g_al [b*2048+l][d]
// ---------------------------------------------------------------------------
__global__ __launch_bounds__(256) void transpose_convert_y()
{
    __shared__ float tile[32][33];
    const int tx = threadIdx.x & 31;
    const int ty = threadIdx.x >> 5;
    const int l0 = blockIdx.x * 32;
    const int d0 = blockIdx.y * 32;
    const int b  = blockIdx.z;

#pragma unroll
    for (int i = 0; i < 4; i++) {
        int d = d0 + ty + i * 8;
        tile[ty + i * 8][tx] = g_y[((size_t)(b * DMODEL + d) << 11) + l0 + tx];
    }
    __syncthreads();
#pragma unroll
    for (int i = 0; i < 4; i++) {
        int l = l0 + ty + i * 8;
        float v = tile[tx][ty + i * 8];
        __half h = __float2half_rn(v);
        __half w = __float2half_rn(v - __half2float(h));
        size_t o = ((size_t)((b << 11) + l)) * DMODEL + d0 + tx;
        g_ah[o] = h;
        g_al[o] = w;
    }
}

// ---------------------------------------------------------------------------
// Split-fp16 HMMA GEMM:  D[m,n] = sum_k A[m,k]*B[n,k]   (fp32 via hi/lo split)
// CTA tile 128x128, K-chunk 64 (128B rows, XOR-swizzled), 2-stage cp.async.
// 8 warps in 4(M) x 2(N); warp = 32x64 = 2 x 8 m16n8k16 atoms.
// MODE 1: A=W_in (m=d), B=activations (n=token); epilogue -> g_u[b][d][l]
// MODE 2: A=activations (m=token), B=W_out (n=d);  epilogue -> Cout row-major
// ---------------------------------------------------------------------------
#define STAGE_BYTES 65536           // 4 arrays x 16 KB
#define SMEM_BYTES  (2 * STAGE_BYTES)

template <int MODE>
__global__ __launch_bounds__(256, 1) void gemm_mma(const __half* __restrict__ Abase_h,
                                                   const __half* __restrict__ Abase_l,
                                                   const __half* __restrict__ Bbase_h,
                                                   const __half* __restrict__ Bbase_l,
                                                   const float* __restrict__ bias,
                                                   float* __restrict__ Cout)
{
    extern __shared__ __align__(1024) char dyn[];
    const uint32_t sb = smem_u32(dyn);
    const int tid  = threadIdx.x;
    const int wid  = tid >> 5;
    const int lane = tid & 31;
    const int wm = wid & 3;          // 4 M-groups of 32 rows
    const int wn = wid >> 2;         // 2 N-groups of 64 cols
    const int n0 = blockIdx.x * 128;
    const int m0 = blockIdx.y * 128;

    const __half* Ah = Abase_h + (size_t)m0 * 512;
    const __half* Al = Abase_l + (size_t)m0 * 512;
    const __half* Bh = Bbase_h + (size_t)n0 * 512;
    const __half* Bl = Bbase_l + (size_t)n0 * 512;

    // stage loader: 1024 16B chunks per array
    auto load_stage = [&](int stage, int c) {
        const int k0 = c * 64;
        const uint32_t sbase = sb + stage * STAGE_BYTES;
#pragma unroll
        for (int i = 0; i < 4; i++) {
            const int idx = i * 256 + tid;
            const int r  = idx >> 3;
            const int ch = idx & 7;
            const uint32_t so = (uint32_t)((r * 128 + ch * 16) ^ ((r & 7) << 4));
            const size_t go = (size_t)r * 512 + k0 + ch * 8;
            cpasync16(sbase + so,         Ah + go);
            cpasync16(sbase + 16384 + so, Al + go);
            cpasync16(sbase + 32768 + so, Bh + go);
            cpasync16(sbase + 49152 + so, Bl + go);
        }
        cp_commit();
    };

    float c[2][8][4];
#pragma unroll
    for (int mi = 0; mi < 2; mi++)
#pragma unroll
        for (int ni = 0; ni < 8; ni++)
#pragma unroll
            for (int j = 0; j < 4; j++) c[mi][ni][j] = 0.0f;

    load_stage(0, 0);
    load_stage(1, 1);

    const int grp = lane >> 3;
    const int sub = lane & 7;

#pragma unroll 1
    for (int cch = 0; cch < 8; cch++) {
        if (cch == 7) asm volatile("cp.async.wait_group 0;" ::: "memory");
        else          asm volatile("cp.async.wait_group 1;" ::: "memory");
        __syncthreads();

        const uint32_t sa = sb + (cch & 1) * STAGE_BYTES;

#pragma unroll
        for (int s = 0; s < 4; s++) {
            uint32_t aH[2][4], aL[2][4], bH[4][4], bL[4][4];
#pragma unroll
            for (int mi = 0; mi < 2; mi++) {
                const int rowA = wm * 32 + mi * 16 + (grp & 1) * 8 + sub;
                const int kbA  = s * 32 + (grp >> 1) * 16;
                const uint32_t off = (uint32_t)((rowA * 128 + kbA) ^ ((rowA & 7) << 4));
                ldsm4(sa + off,         aH[mi]);
                ldsm4(sa + 16384 + off, aL[mi]);
            }
#pragma unroll
            for (int p = 0; p < 4; p++) {
                const int atom = 2 * p + (grp >> 1);
                const int rowB = wn * 64 + atom * 8 + sub;
                const int kbB  = s * 32 + (grp & 1) * 16;
                const uint32_t off = (uint32_t)((rowB * 128 + kbB) ^ ((rowB & 7) << 4));
                ldsm4(sa + 32768 + off, bH[p]);
                ldsm4(sa + 49152 + off, bL[p]);
            }
#pragma unroll
            for (int mi = 0; mi < 2; mi++)
#pragma unroll
                for (int p = 0; p < 4; p++) {
                    mma16816(c[mi][2 * p + 0], aH[mi], &bH[p][0]);
                    mma16816(c[mi][2 * p + 1], aH[mi], &bH[p][2]);
                    mma16816(c[mi][2 * p + 0], aH[mi], &bL[p][0]);
                    mma16816(c[mi][2 * p + 1], aH[mi], &bL[p][2]);
                    mma16816(c[mi][2 * p + 0], aL[mi], &bH[p][0]);
                    mma16816(c[mi][2 * p + 1], aL[mi], &bH[p][2]);
                }
        }
        __syncthreads();
        if (cch + 2 < 8) load_stage(cch & 1, cch + 2);
    }

    // ------------------------- epilogue -------------------------
    const int q  = lane >> 2;          // row within 8
    const int t2 = (lane & 3) * 2;     // col pair within 8

    if (MODE == 1) {
        const int b  = n0 >> 11;
        const int lt = (n0 & 2047) + wn * 64;
#pragma unroll
        for (int mi = 0; mi < 2; mi++)
#pragma unroll
            for (int rr = 0; rr < 2; rr++) {
                const int d_row = m0 + wm * 32 + mi * 16 + rr * 8 + q;
                const float bi = __ldg(bias + d_row);
                float* dst = g_u + ((size_t)(b * DMODEL + d_row) << 11) + lt;
#pragma unroll
                for (int ni = 0; ni < 8; ni++) {
                    float2 v;
                    v.x = c[mi][ni][rr * 2 + 0] + bi;
                    v.y = c[mi][ni][rr * 2 + 1] + bi;
                    *(float2*)(dst + ni * 8 + t2) = v;
                }
            }
    } else {
#pragma unroll
        for (int mi = 0; mi < 2; mi++)
#pragma unroll
            for (int rr = 0; rr < 2; rr++) {
                const int row = m0 + wm * 32 + mi * 16 + rr * 8 + q;
                float* dst = Cout + (size_t)row * 512 + n0 + wn * 64;
#pragma unroll
                for (int ni = 0; ni < 8; ni++) {
                    const float2 bv = *(const float2*)(bias + n0 + wn * 64 + ni * 8 + t2);
                    float2 v;
                    v.x = c[mi][ni][rr * 2 + 0] + bv.x;
                    v.y = c[mi][ni][rr * 2 + 1] + bv.y;
                    *(float2*)(dst + ni * 8 + t2) = v;
                }
            }
    }
}

// ---------------------------------------------------------------------------
// SSM recurrence scan (proven): one warp per (b,d); 2 states/lane.
// ---------------------------------------------------------------------------
__global__ __launch_bounds__(256) void s4_scan(const float* __restrict__ A_log,
                                               const float* __restrict__ Bp,
                                               const float* __restrict__ Cp,
                                               const float* __restrict__ Dp,
                                               const float* __restrict__ dt)
{
    const int warp = (blockIdx.x * blockDim.x + threadIdx.x) >> 5;
    const int lane = threadIdx.x & 31;
    const int d = warp & (DMODEL - 1);
    const int b = warp >> 9;

    const float dtd = dt[d];
    const int i0 = d * DSTATE + lane;
    const int i1 = i0 + 32;

    const float r0 = expf(-expf(A_log[i0]) * dtd);
    const float r1 = expf(-expf(A_log[i1]) * dtd);
    const float c0 = Cp[i0] * Bp[i0] * dtd;
    const float c1 = Cp[i1] * Bp[i1] * dtd;
    const float Dd = Dp[d];

    const float* ub = g_u + ((size_t)(b * DMODEL + d) << 11);
    float*       yb = g_y + ((size_t)(b * DMODEL + d) << 11);

    float z0 = 0.0f, z1 = 0.0f;

    for (int t0 = 0; t0 < SEQLEN; t0 += 32) {
        const float uv = ub[t0 + lane];
        float p[32];
#pragma unroll
        for (int i = 0; i < 32; i++) {
            const float uu = __shfl_sync(0xffffffffu, uv, i);
            z0 = fmaf(r0, z0, uu);
            z1 = fmaf(r1, z1, uu);
            p[i] = fmaf(c0, z0, c1 * z1);
        }
        const bool h16 = (lane & 16);
        float s16[16];
#pragma unroll
        for (int k = 0; k < 16; k++) {
            const float keep = h16 ? p[k + 16] : p[k];
            const float send = h16 ? p[k] : p[k + 16];
            s16[k] = keep + __shfl_xor_sync(0xffffffffu, send, 16);
        }
        const bool h8 = (lane & 8);
        float s8[8];
#pragma unroll
        for (int k = 0; k < 8; k++) {
            const float keep = h8 ? s16[k + 8] : s16[k];
            const float send = h8 ? s16[k] : s16[k + 8];
            s8[k] = keep + __shfl_xor_sync(0xffffffffu, send, 8);
        }
        const bool h4 = (lane & 4);
        float s4[4];
#pragma unroll
        for (int k = 0; k < 4; k++) {
            const float keep = h4 ? s8[k + 4] : s8[k];
            const float send = h4 ? s8[k] : s8[k + 4];
            s4[k] = keep + __shfl_xor_sync(0xffffffffu, send, 4);
        }
        const bool h2 = (lane & 2);
        float s2[2];
#pragma unroll
        for (int k = 0; k < 2; k++) {
            const float keep = h2 ? s4[k + 2] : s4[k];
            const float send = h2 ? s4[k] : s4[k + 2];
            s2[k] = keep + __shfl_xor_sync(0xffffffffu, send, 2);
        }
        const bool h1 = (lane & 1);
        const float keep = h1 ? s2[1] : s2[0];
        const float send = h1 ? s2[0] : s2[1];
        const float tot = keep + __shfl_xor_sync(0xffffffffu, send, 1);

        yb[t0 + lane] = fmaf(Dd, uv, tot);
    }
}

// ---------------------------------------------------------------------------
extern "C" void kernel_launch(void* const* d_in, const int* in_sizes, int n_in,
                              void* d_out, int out_size)
{
    const float* x     = (const float*)d_in[0];
    const float* W_in  = (const float*)d_in[1];
    const float* b_in  = (const float*)d_in[2];
    const float* A_log = (const float*)d_in[3];
    const float* B     = (const float*)d_in[4];
    const float* C     = (const float*)d_in[5];
    const float* D     = (const float*)d_in[6];
    const float* dt    = (const float*)d_in[7];
    const float* W_out = (const float*)d_in[8];
    const float* b_out = (const float*)d_in[9];
    float* out = (float*)d_out;

    static bool attr_done = false;
    if (!attr_done) {
        cudaFuncSetAttribute(gemm_mma<1>, cudaFuncAttributeMaxDynamicSharedMemorySize, SMEM_BYTES);
        cudaFuncSetAttribute(gemm_mma<2>, cudaFuncAttributeMaxDynamicSharedMemorySize, SMEM_BYTES);
        attr_done = true;
    }

    __half *p_ah, *p_al, *p_wh, *p_wl;
    cudaGetSymbolAddress((void**)&p_ah, g_ah);
    cudaGetSymbolAddress((void**)&p_al, g_al);
    cudaGetSymbolAddress((void**)&p_wh, g_wh);
    cudaGetSymbolAddress((void**)&p_wl, g_wl);

    // 1) split-convert activations and weights to fp16 hi/lo
    convert_split<<<(MTOT * DMODEL / 4 + 255) / 256, 256>>>(x, p_ah, p_al, MTOT * DMODEL / 4);
    convert_split<<<(DMODEL * DMODEL / 4 + 255) / 256, 256>>>(W_in, p_wh, p_wl,
                                                              DMODEL * DMODEL / 4);
    convert_split<<<(DMODEL * DMODEL / 4 + 255) / 256, 256>>>(
        W_out, p_wh + DMODEL * DMODEL, p_wl + DMODEL * DMODEL, DMODEL * DMODEL / 4);

    // 2) in_proj on tensor cores: D[d, token] -> g_u[b][d][l]
    {
        dim3 g(MTOT / 128, DMODEL / 128);   // (64, 4)
        gemm_mma<1><<<g, 256, SMEM_BYTES>>>(p_wh, p_wl, p_ah, p_al, b_in, nullptr);
    }

    // 3) SSM recurrence: g_u -> g_y  [b][d][l]
    s4_scan<<<(BATCH * DMODEL) / 8, 256>>>(A_log, B, C, D, dt);

    // 4) transpose + split-convert y -> [token][d] fp16 hi/lo
    {
        dim3 g(SEQLEN / 32, DMODEL / 32, BATCH);   // (64, 16, 4)
        transpose_convert_y<<<g, 256>>>();
    }

    // 5) out_proj on tensor cores: D[token, d] -> out
    {
        dim3 g(DMODEL / 128, MTOT / 128);   // (4, 64)
        gemm_mma<2><<<g, 256, SMEM_BYTES>>>(p_ah, p_al, p_wh + DMODEL * DMODEL,
                                            p_wl + DMODEL * DMODEL, b_out, out);
    }
}

// round 5
// speedup vs baseline: 2.7804x; 1.0140x over previous
#include <cuda_runtime.h>
#include <cuda_fp16.h>
#include <math.h>
#include <stdint.h>

// Problem constants
#define BATCH   4
#define SEQLEN  2048
#define DMODEL  512
#define DSTATE  64
#define MTOT    (BATCH * SEQLEN)   // 8192

// ---------------------------------------------------------------------------
// Device scratch (no cudaMalloc allowed)
// ---------------------------------------------------------------------------
__device__ float g_u[BATCH * DMODEL * SEQLEN];    // [b][d][l] fp32
__device__ float g_y[BATCH * DMODEL * SEQLEN];    // [b][d][l] fp32
__device__ __half g_ah[MTOT * DMODEL];            // activations hi [m][k]
__device__ __half g_al[MTOT * DMODEL];            // activations lo [m][k]
__device__ __half g_wh[2 * DMODEL * DMODEL];      // W_in | W_out hi
__device__ __half g_wl[2 * DMODEL * DMODEL];      // W_in | W_out lo

// ---------------------------------------------------------------------------
// PTX helpers
// ---------------------------------------------------------------------------
__device__ __forceinline__ uint32_t smem_u32(const void* p) {
    uint32_t a;
    asm("{ .reg .u64 t; cvta.to.shared.u64 t, %1; cvt.u32.u64 %0, t; }" : "=r"(a) : "l"(p));
    return a;
}
__device__ __forceinline__ void cpasync16(uint32_t s, const void* g) {
    asm volatile("cp.async.cg.shared.global [%0], [%1], 16;" :: "r"(s), "l"(g));
}
__device__ __forceinline__ void cp_commit() {
    asm volatile("cp.async.commit_group;" ::: "memory");
}
__device__ __forceinline__ void ldsm4(uint32_t a, uint32_t* r) {
    asm volatile("ldmatrix.sync.aligned.m8n8.x4.shared.b16 {%0,%1,%2,%3}, [%4];"
                 : "=r"(r[0]), "=r"(r[1]), "=r"(r[2]), "=r"(r[3]) : "r"(a));
}
__device__ __forceinline__ void mma16816(float* c, const uint32_t* a, const uint32_t* b) {
    asm volatile(
        "mma.sync.aligned.m16n8k16.row.col.f32.f16.f16.f32 "
        "{%0,%1,%2,%3}, {%4,%5,%6,%7}, {%8,%9}, {%0,%1,%2,%3};"
        : "+f"(c[0]), "+f"(c[1]), "+f"(c[2]), "+f"(c[3])
        : "r"(a[0]), "r"(a[1]), "r"(a[2]), "r"(a[3]), "r"(b[0]), "r"(b[1]));
}

// ---------------------------------------------------------------------------
// Merged split-precision conversion for x, W_in, W_out (one launch)
// ---------------------------------------------------------------------------
#define N4_X (MTOT * DMODEL / 4)
#define N4_W (DMODEL * DMODEL / 4)

__global__ __launch_bounds__(256) void convert_all(const float* __restrict__ x,
                                                   const float* __restrict__ w_in,
                                                   const float* __restrict__ w_out,
                                                   __half* __restrict__ ah,
                                                   __half* __restrict__ al,
                                                   __half* __restrict__ wh,
                                                   __half* __restrict__ wl)
{
    int i = blockIdx.x * 256 + threadIdx.x;
    const float* src;
    __half *dh, *dl;
    int off;
    if (i < N4_X) {
        src = x; dh = ah; dl = al; off = i;
    } else if (i < N4_X + N4_W) {
        src = w_in; dh = wh; dl = wl; off = i - N4_X;
    } else if (i < N4_X + 2 * N4_W) {
        src = w_out; dh = wh + DMODEL * DMODEL; dl = wl + DMODEL * DMODEL;
        off = i - N4_X - N4_W;
    } else return;

    float4 v = ((const float4*)src)[off];
    __half h0 = __float2half_rn(v.x);
    __half h1 = __float2half_rn(v.y);
    __half h2 = __float2half_rn(v.z);
    __half h3 = __float2half_rn(v.w);
    __half l0 = __float2half_rn(v.x - __half2float(h0));
    __half l1 = __float2half_rn(v.y - __half2float(h1));
    __half l2 = __float2half_rn(v.z - __half2float(h2));
    __half l3 = __float2half_rn(v.w - __half2float(h3));
    uint2 ph, pl;
    ph.x = (uint32_t)__half_as_ushort(h0) | ((uint32_t)__half_as_ushort(h1) << 16);
    ph.y = (uint32_t)__half_as_ushort(h2) | ((uint32_t)__half_as_ushort(h3) << 16);
    pl.x = (uint32_t)__half_as_ushort(l0) | ((uint32_t)__half_as_ushort(l1) << 16);
    pl.y = (uint32_t)__half_as_ushort(l2) | ((uint32_t)__half_as_ushort(l3) << 16);
    ((uint2*)dh)[off] = ph;
    ((uint2*)dl)[off] = pl;
}

// ---------------------------------------------------------------------------
// Transpose + split-convert: g_y [b][d][l] fp32 -> g_ah/g_al [b*2048+l][d]
// ---------------------------------------------------------------------------
__global__ __launch_bounds__(256) void transpose_convert_y()
{
    __shared__ float tile[32][33];
    const int tx = threadIdx.x & 31;
    const int ty = threadIdx.x >> 5;
    const int l0 = blockIdx.x * 32;
    const int d0 = blockIdx.y * 32;
    const int b  = blockIdx.z;

#pragma unroll
    for (int i = 0; i < 4; i++) {
        int d = d0 + ty + i * 8;
        tile[ty + i * 8][tx] = g_y[((size_t)(b * DMODEL + d) << 11) + l0 + tx];
    }
    __syncthreads();
#pragma unroll
    for (int i = 0; i < 4; i++) {
        int l = l0 + ty + i * 8;
        float v = tile[tx][ty + i * 8];
        __half h = __float2half_rn(v);
        __half w = __float2half_rn(v - __half2float(h));
        size_t o = ((size_t)((b << 11) + l)) * DMODEL + d0 + tx;
        g_ah[o] = h;
        g_al[o] = w;
    }
}

// ---------------------------------------------------------------------------
// Split-fp16 HMMA GEMM:  D[m,n] = sum_k A[m,k]*B[n,k]   (fp32 via hi/lo split)
// CTA tile 128x128, K-chunk 64 (XOR-swizzled 128B rows), 3-stage cp.async,
// register fragment double-buffering across s-steps.
// 8 warps in 4(M) x 2(N); warp = 32x64.
// MODE 1: A=W_in (m=d), B=activations (n=token); epilogue -> g_u[b][d][l]
// MODE 2: A=activations (m=token), B=W_out (n=d);  epilogue -> Cout row-major
// ---------------------------------------------------------------------------
#define STAGE_BYTES 65536            // 4 arrays x 16 KB
#define NSTAGE 3
#define SMEM_BYTES (NSTAGE * STAGE_BYTES)

__device__ __forceinline__ void ld_frags(uint32_t sa, int s, int wm, int wn,
                                         int grp, int sub,
                                         uint32_t aH[2][4], uint32_t aL[2][4],
                                         uint32_t bH[4][4], uint32_t bL[4][4])
{
#pragma unroll
    for (int mi = 0; mi < 2; mi++) {
        const int rowA = wm * 32 + mi * 16 + (grp & 1) * 8 + sub;
        const int kbA  = s * 32 + (grp >> 1) * 16;
        const uint32_t off = (uint32_t)((rowA * 128 + kbA) ^ ((rowA & 7) << 4));
        ldsm4(sa + off,         aH[mi]);
        ldsm4(sa + 16384 + off, aL[mi]);
    }
#pragma unroll
    for (int p = 0; p < 4; p++) {
        const int atom = 2 * p + (grp >> 1);
        const int rowB = wn * 64 + atom * 8 + sub;
        const int kbB  = s * 32 + (grp & 1) * 16;
        const uint32_t off = (uint32_t)((rowB * 128 + kbB) ^ ((rowB & 7) << 4));
        ldsm4(sa + 32768 + off, bH[p]);
        ldsm4(sa + 49152 + off, bL[p]);
    }
}

template <int MODE>
__global__ __launch_bounds__(256, 1) void gemm_mma(const __half* __restrict__ Abase_h,
                                                   const __half* __restrict__ Abase_l,
                                                   const __half* __restrict__ Bbase_h,
                                                   const __half* __restrict__ Bbase_l,
                                                   const float* __restrict__ bias,
                                                   float* __restrict__ Cout)
{
    extern __shared__ __align__(1024) char dyn[];
    const uint32_t sb = smem_u32(dyn);
    const int tid  = threadIdx.x;
    const int wid  = tid >> 5;
    const int lane = tid & 31;
    const int wm = wid & 3;
    const int wn = wid >> 2;
    const int n0 = blockIdx.x * 128;
    const int m0 = blockIdx.y * 128;

    const __half* Ah = Abase_h + (size_t)m0 * 512;
    const __half* Al = Abase_l + (size_t)m0 * 512;
    const __half* Bh = Bbase_h + (size_t)n0 * 512;
    const __half* Bl = Bbase_l + (size_t)n0 * 512;

    auto load_stage = [&](int stage, int c) {
        const int k0 = c * 64;
        const uint32_t sbase = sb + stage * STAGE_BYTES;
#pragma unroll
        for (int i = 0; i < 4; i++) {
            const int idx = i * 256 + tid;
            const int r  = idx >> 3;
            const int ch = idx & 7;
            const uint32_t so = (uint32_t)((r * 128 + ch * 16) ^ ((r & 7) << 4));
            const size_t go = (size_t)r * 512 + k0 + ch * 8;
            cpasync16(sbase + so,         Ah + go);
            cpasync16(sbase + 16384 + so, Al + go);
            cpasync16(sbase + 32768 + so, Bh + go);
            cpasync16(sbase + 49152 + so, Bl + go);
        }
        cp_commit();
    };

    float c[2][8][4];
#pragma unroll
    for (int mi = 0; mi < 2; mi++)
#pragma unroll
        for (int ni = 0; ni < 8; ni++)
#pragma unroll
            for (int j = 0; j < 4; j++) c[mi][ni][j] = 0.0f;

    load_stage(0, 0);
    load_stage(1, 1);

    const int grp = lane >> 3;
    const int sub = lane & 7;

#pragma unroll 1
    for (int cch = 0; cch < 8; cch++) {
        // issue load for chunk cch+2 into stage (cch+2)%3 (held chunk cch-1,
        // whose compute finished before the trailing sync of the last iter)
        if (cch + 2 < 8) load_stage((cch + 2) % NSTAGE, cch + 2);

        if (cch < 6)       asm volatile("cp.async.wait_group 2;" ::: "memory");
        else if (cch == 6) asm volatile("cp.async.wait_group 1;" ::: "memory");
        else               asm volatile("cp.async.wait_group 0;" ::: "memory");
        __syncthreads();

        const uint32_t sa = sb + (cch % NSTAGE) * STAGE_BYTES;

        uint32_t aH[2][2][4], aL[2][2][4], bH[2][4][4], bL[2][4][4];
        ld_frags(sa, 0, wm, wn, grp, sub, aH[0], aL[0], bH[0], bL[0]);

#pragma unroll
        for (int s = 0; s < 4; s++) {
            const int cur = s & 1;
            const int nxt = cur ^ 1;
            if (s < 3) ld_frags(sa, s + 1, wm, wn, grp, sub,
                                aH[nxt], aL[nxt], bH[nxt], bL[nxt]);
#pragma unroll
            for (int mi = 0; mi < 2; mi++)
#pragma unroll
                for (int p = 0; p < 4; p++) {
                    mma16816(c[mi][2 * p + 0], aH[cur][mi], &bH[cur][p][0]);
                    mma16816(c[mi][2 * p + 1], aH[cur][mi], &bH[cur][p][2]);
                    mma16816(c[mi][2 * p + 0], aH[cur][mi], &bL[cur][p][0]);
                    mma16816(c[mi][2 * p + 1], aH[cur][mi], &bL[cur][p][2]);
                    mma16816(c[mi][2 * p + 0], aL[cur][mi], &bH[cur][p][0]);
                    mma16816(c[mi][2 * p + 1], aL[cur][mi], &bH[cur][p][2]);
                }
        }
        __syncthreads();
    }

    // ------------------------- epilogue -------------------------
    const int q  = lane >> 2;
    const int t2 = (lane & 3) * 2;

    if (MODE == 1) {
        const int b  = n0 >> 11;
        const int lt = (n0 & 2047) + wn * 64;
#pragma unroll
        for (int mi = 0; mi < 2; mi++)
#pragma unroll
            for (int rr = 0; rr < 2; rr++) {
                const int d_row = m0 + wm * 32 + mi * 16 + rr * 8 + q;
                const float bi = __ldg(bias + d_row);
                float* dst = g_u + ((size_t)(b * DMODEL + d_row) << 11) + lt;
#pragma unroll
                for (int ni = 0; ni < 8; ni++) {
                    float2 v;
                    v.x = c[mi][ni][rr * 2 + 0] + bi;
                    v.y = c[mi][ni][rr * 2 + 1] + bi;
                    *(float2*)(dst + ni * 8 + t2) = v;
                }
            }
    } else {
#pragma unroll
        for (int mi = 0; mi < 2; mi++)
#pragma unroll
            for (int rr = 0; rr < 2; rr++) {
                const int row = m0 + wm * 32 + mi * 16 + rr * 8 + q;
                float* dst = Cout + (size_t)row * 512 + n0 + wn * 64;
#pragma unroll
                for (int ni = 0; ni < 8; ni++) {
                    const float2 bv = *(const float2*)(bias + n0 + wn * 64 + ni * 8 + t2);
                    float2 v;
                    v.x = c[mi][ni][rr * 2 + 0] + bv.x;
                    v.y = c[mi][ni][rr * 2 + 1] + bv.y;
                    *(float2*)(dst + ni * 8 + t2) = v;
                }
            }
    }
}

// ---------------------------------------------------------------------------
// SSM recurrence scan (proven): one warp per (b,d); 2 states/lane.
// ---------------------------------------------------------------------------
__global__ __launch_bounds__(256) void s4_scan(const float* __restrict__ A_log,
                                               const float* __restrict__ Bp,
                                               const float* __restrict__ Cp,
                                               const float* __restrict__ Dp,
                                               const float* __restrict__ dt)
{
    const int warp = (blockIdx.x * blockDim.x + threadIdx.x) >> 5;
    const int lane = threadIdx.x & 31;
    const int d = warp & (DMODEL - 1);
    const int b = warp >> 9;

    const float dtd = dt[d];
    const int i0 = d * DSTATE + lane;
    const int i1 = i0 + 32;

    const float r0 = expf(-expf(A_log[i0]) * dtd);
    const float r1 = expf(-expf(A_log[i1]) * dtd);
    const float c0 = Cp[i0] * Bp[i0] * dtd;
    const float c1 = Cp[i1] * Bp[i1] * dtd;
    const float Dd = Dp[d];

    const float* ub = g_u + ((size_t)(b * DMODEL + d) << 11);
    float*       yb = g_y + ((size_t)(b * DMODEL + d) << 11);

    float z0 = 0.0f, z1 = 0.0f;

    for (int t0 = 0; t0 < SEQLEN; t0 += 32) {
        const float uv = ub[t0 + lane];
        float p[32];
#pragma unroll
        for (int i = 0; i < 32; i++) {
            const float uu = __shfl_sync(0xffffffffu, uv, i);
            z0 = fmaf(r0, z0, uu);
            z1 = fmaf(r1, z1, uu);
            p[i] = fmaf(c0, z0, c1 * z1);
        }
        const bool h16 = (lane & 16);
        float s16[16];
#pragma unroll
        for (int k = 0; k < 16; k++) {
            const float keep = h16 ? p[k + 16] : p[k];
            const float send = h16 ? p[k] : p[k + 16];
            s16[k] = keep + __shfl_xor_sync(0xffffffffu, send, 16);
        }
        const bool h8 = (lane & 8);
        float s8[8];
#pragma unroll
        for (int k = 0; k < 8; k++) {
            const float keep = h8 ? s16[k + 8] : s16[k];
            const float send = h8 ? s16[k] : s16[k + 8];
            s8[k] = keep + __shfl_xor_sync(0xffffffffu, send, 8);
        }
        const bool h4 = (lane & 4);
        float s4[4];
#pragma unroll
        for (int k = 0; k < 4; k++) {
            const float keep = h4 ? s8[k + 4] : s8[k];
            const float send = h4 ? s8[k] : s8[k + 4];
            s4[k] = keep + __shfl_xor_sync(0xffffffffu, send, 4);
        }
        const bool h2 = (lane & 2);
        float s2[2];
#pragma unroll
        for (int k = 0; k < 2; k++) {
            const float keep = h2 ? s4[k + 2] : s4[k];
            const float send = h2 ? s4[k] : s4[k + 2];
            s2[k] = keep + __shfl_xor_sync(0xffffffffu, send, 2);
        }
        const bool h1 = (lane & 1);
        const float keep = h1 ? s2[1] : s2[0];
        const float send = h1 ? s2[0] : s2[1];
        const float tot = keep + __shfl_xor_sync(0xffffffffu, send, 1);

        yb[t0 + lane] = fmaf(Dd, uv, tot);
    }
}

// ---------------------------------------------------------------------------
extern "C" void kernel_launch(void* const* d_in, const int* in_sizes, int n_in,
                              void* d_out, int out_size)
{
    const float* x     = (const float*)d_in[0];
    const float* W_in  = (const float*)d_in[1];
    const float* b_in  = (const float*)d_in[2];
    const float* A_log = (const float*)d_in[3];
    const float* B     = (const float*)d_in[4];
    const float* C     = (const float*)d_in[5];
    const float* D     = (const float*)d_in[6];
    const float* dt    = (const float*)d_in[7];
    const float* W_out = (const float*)d_in[8];
    const float* b_out = (const float*)d_in[9];
    float* out = (float*)d_out;

    static bool attr_done = false;
    if (!attr_done) {
        cudaFuncSetAttribute(gemm_mma<1>, cudaFuncAttributeMaxDynamicSharedMemorySize, SMEM_BYTES);
        cudaFuncSetAttribute(gemm_mma<2>, cudaFuncAttributeMaxDynamicSharedMemorySize, SMEM_BYTES);
        attr_done = true;
    }

    __half *p_ah, *p_al, *p_wh, *p_wl;
    cudaGetSymbolAddress((void**)&p_ah, g_ah);
    cudaGetSymbolAddress((void**)&p_al, g_al);
    cudaGetSymbolAddress((void**)&p_wh, g_wh);
    cudaGetSymbolAddress((void**)&p_wl, g_wl);

    // 1) split-convert x + W_in + W_out (single launch)
    {
        const int total = N4_X + 2 * N4_W;
        convert_all<<<(total + 255) / 256, 256>>>(x, W_in, W_out, p_ah, p_al, p_wh, p_wl);
    }

    // 2) in_proj on tensor cores: D[d, token] -> g_u[b][d][l]
    {
        dim3 g(MTOT / 128, DMODEL / 128);   // (64, 4)
        gemm_mma<1><<<g, 256, SMEM_BYTES>>>(p_wh, p_wl, p_ah, p_al, b_in, nullptr);
    }

    // 3) SSM recurrence: g_u -> g_y  [b][d][l]
    s4_scan<<<(BATCH * DMODEL) / 8, 256>>>(A_log, B, C, D, dt);

    // 4) transpose + split-convert y -> [token][d] fp16 hi/lo
    {
        dim3 g(SEQLEN / 32, DMODEL / 32, BATCH);   // (64, 16, 4)
        transpose_convert_y<<<g, 256>>>();
    }

    // 5) out_proj on tensor cores: D[token, d] -> out
    {
        dim3 g(DMODEL / 128, MTOT / 128);   // (4, 64)
        gemm_mma<2><<<g, 256, SMEM_BYTES>>>(p_ah, p_al, p_wh + DMODEL * DMODEL,
                                            p_wl + DMODEL * DMODEL, b_out, out);
    }
}